// round 10
// baseline (speedup 1.0000x reference)
#include <cuda_runtime.h>
#include <cuda_bf16.h>
#include <stdint.h>
#include <math.h>

#define BSZ 32
#define CSZ 256
#define HH  56
#define WFQ 32
#define WWK 62
#define NPIX 3136
#define MSZ 16
#define KSZ 8
#define HIDN 16
#define PI_D 3.141592653589793238462643383279502884

typedef unsigned long long ull;

__device__ __forceinline__ ull d_fma2(ull a, ull b, ull c) {
    ull d;
    asm("fma.rn.f32x2 %0, %1, %2, %3;" : "=l"(d) : "l"(a), "l"(b), "l"(c));
    return d;
}
__device__ __forceinline__ ull d_dup(float x) {
    ull r;
    asm("mov.b64 %0, {%1, %1};" : "=l"(r) : "f"(x));
    return r;
}
__device__ __forceinline__ float2 d_unpack(ull v) {
    float2 r;
    asm("mov.b64 {%0, %1}, %2;" : "=f"(r.x), "=f"(r.y) : "l"(v));
    return r;
}
__device__ __forceinline__ void mma_bf16(float* d, const uint32_t* a, const uint32_t* b) {
    asm("mma.sync.aligned.m16n8k16.row.col.f32.bf16.bf16.f32 "
        "{%0,%1,%2,%3}, {%4,%5,%6,%7}, {%8,%9}, {%0,%1,%2,%3};"
        : "+f"(d[0]), "+f"(d[1]), "+f"(d[2]), "+f"(d[3])
        : "r"(a[0]), "r"(a[1]), "r"(a[2]), "r"(a[3]), "r"(b[0]), "r"(b[1]));
}
__device__ __forceinline__ void bsplit(float v, __nv_bfloat16& hi, __nv_bfloat16& lo) {
    hi = __float2bfloat16(v);
    lo = __float2bfloat16(v - __bfloat162float(hi));
}
__device__ __forceinline__ void lda_frags(const __nv_bfloat16* P, int stride, int r0, int cb, uint32_t* f) {
    f[0] = *(const uint32_t*)&P[r0 * stride + cb];
    f[1] = *(const uint32_t*)&P[(r0 + 8) * stride + cb];
    f[2] = *(const uint32_t*)&P[r0 * stride + cb + 8];
    f[3] = *(const uint32_t*)&P[(r0 + 8) * stride + cb + 8];
}
__device__ __forceinline__ void ldb_frag(const __nv_bfloat16* P, int stride, int n0, int cb, uint32_t* f) {
    f[0] = *(const uint32_t*)&P[n0 * stride + cb];
    f[1] = *(const uint32_t*)&P[n0 * stride + cb + 8];
}

// ----------------------------- device scratch -------------------------------
__device__ float  g_ctx[BSZ * CSZ];
__device__ float  g_hact[BSZ * HIDN];
__device__ float  g_coeffs[BSZ * CSZ * MSZ * KSZ];
__device__ float  g_yspec[(size_t)BSZ * CSZ * NPIX];
__device__ float  g_yconv[(size_t)BSZ * CSZ * NPIX];
__device__ float  g_bnA[CSZ], g_bnB[CSZ];
__device__ __nv_bfloat16 g_whl[2][CSZ * CSZ];

__device__ float2 g_FwRT[HH * WFQ];
__device__ float2 g_Fh[HH * HH];
__device__ float2 g_Gh[HH * HH];
__device__ float2 g_GwT[WFQ * HH];
__device__ float2 g_CS[29 * HH];     // (cos,sin)(2*pi*p*j/56), p=0..28

__device__ double g_Rf[WWK * HH];
__device__ double g_Rb[HH * WWK];
__device__ double g_tw62r[WWK], g_tw62i[WWK];

__device__ double rz_fwd(int j, int i) {
    double s = (j + 0.5) * (56.0 / 62.0) - 0.5;
    double w = fmax(0.0, 1.0 - fabs(s - (double)i));
    double denom = 0.0;
    int i0 = (int)floor(s);
    for (int q = i0; q <= i0 + 1; ++q)
        if (q >= 0 && q < 56) denom += fmax(0.0, 1.0 - fabs(s - (double)q));
    return w / denom;
}
__device__ double rz_bwd(int j, int i) {
    double ks = 62.0 / 56.0;
    double s = (j + 0.5) * ks - 0.5;
    double w = fmax(0.0, 1.0 - fabs(s - (double)i) / ks);
    double denom = 0.0;
    int lo = (int)ceil(s - ks), hi = (int)floor(s + ks);
    if (lo < 0) lo = 0;
    if (hi > 61) hi = 61;
    for (int q = lo; q <= hi; ++q)
        denom += fmax(0.0, 1.0 - fabs(s - (double)q) / ks);
    return w / denom;
}

__global__ void k_init0() {
    int t = threadIdx.x;
    if (t < WWK) { double a = -2.0 * PI_D * t / 62.0; g_tw62r[t] = cos(a); g_tw62i[t] = sin(a); }
    for (int i = t; i < WWK * HH; i += blockDim.x) g_Rf[i] = rz_fwd(i / HH, i % HH);
    for (int i = t; i < HH * WWK; i += blockDim.x) g_Rb[i] = rz_bwd(i / WWK, i % WWK);
}

__global__ void k_init1() {
    const double SC = 1.0 / sqrt(56.0 * 62.0);
    int total = 1792 + 1792 + 3136 + 3136 + 29 * HH;
    for (int idx = blockIdx.x * blockDim.x + threadIdx.x; idx < total; idx += gridDim.x * blockDim.x) {
        if (idx < 1792) {
            int w0 = idx / WFQ, v = idx % WFQ;
            double ar = 0, ai = 0;
            for (int w = 0; w < WWK; ++w) {
                double r = g_Rf[w * HH + w0]; int m = (v * w) % WWK;
                ar += g_tw62r[m] * r; ai += g_tw62i[m] * r;
            }
            g_FwRT[w0 * WFQ + v] = make_float2((float)(ar * SC), (float)(ai * SC));
        } else if (idx < 3584) {
            int j = idx - 1792; int v = j / HH, w0 = j % HH;
            double cv = (v == 0 || v == 31) ? 1.0 : 2.0;
            double ar = 0, ai = 0;
            for (int w = 0; w < WWK; ++w) {
                double r = g_Rb[w0 * WWK + w]; int m = (v * w) % WWK;
                ar += g_tw62r[m] * r; ai -= g_tw62i[m] * r;
            }
            g_GwT[v * HH + w0] = make_float2((float)(ar * cv * SC), (float)(ai * cv * SC));
        } else if (idx < 6720) {
            int j = idx - 3584; int u = j / HH, h = j % HH;
            double a = -2.0 * PI_D * ((u * h) % HH) / 56.0;
            g_Fh[u * HH + h] = make_float2((float)cos(a), (float)sin(a));
        } else if (idx < 9856) {
            int j = idx - 6720; int h = j / HH, u = j % HH;
            double a = 2.0 * PI_D * ((u * h) % HH) / 56.0;
            g_Gh[h * HH + u] = make_float2((float)cos(a), (float)(sin(a)));
        } else {
            int j = idx - 9856; int p = j / HH, jj = j % HH;
            double a = 2.0 * PI_D * ((p * jj) % HH) / 56.0;
            g_CS[j] = make_float2((float)cos(a), (float)sin(a));
        }
    }
}

__global__ void k_ctx(const float* __restrict__ x) {
    int plane = blockIdx.x;
    const float4* p = (const float4*)(x + (size_t)plane * NPIX);
    float s = 0.f;
    for (int i = threadIdx.x; i < NPIX / 4; i += blockDim.x) {
        float4 v = p[i]; s += v.x + v.y + v.z + v.w;
    }
    for (int o = 16; o > 0; o >>= 1) s += __shfl_xor_sync(0xffffffffu, s, o);
    __shared__ float red[4];
    int warp = threadIdx.x >> 5, lane = threadIdx.x & 31;
    if (lane == 0) red[warp] = s;
    __syncthreads();
    if (threadIdx.x == 0)
        g_ctx[plane] = (red[0] + red[1] + red[2] + red[3]) * (1.0f / NPIX);
}

__global__ void __launch_bounds__(256) k_head1(
    const float* __restrict__ fc1_w, const float* __restrict__ fc1_b,
    const float* __restrict__ ln_g,  const float* __restrict__ ln_b)
{
    int b = blockIdx.x, t = threadIdx.x;
    int warp = t >> 5, lane = t & 31;
    __shared__ float sctx[CSZ];
    __shared__ float shid[HIDN];
    __shared__ float sstat[2];
    sctx[t] = g_ctx[b * CSZ + t];
    __syncthreads();
    for (int rep = 0; rep < 2; ++rep) {
        int hidx = warp * 2 + rep;
        float acc = 0.f;
        for (int c = lane; c < CSZ; c += 32) acc += sctx[c] * fc1_w[hidx * CSZ + c];
        for (int o = 16; o > 0; o >>= 1) acc += __shfl_xor_sync(0xffffffffu, acc, o);
        if (lane == 0) shid[hidx] = acc + fc1_b[hidx];
    }
    __syncthreads();
    if (t == 0) {
        float mu = 0.f;
        for (int i = 0; i < HIDN; ++i) mu += shid[i];
        mu *= (1.0f / HIDN);
        float var = 0.f;
        for (int i = 0; i < HIDN; ++i) { float d = shid[i] - mu; var += d * d; }
        sstat[0] = mu; sstat[1] = rsqrtf(var * (1.0f / HIDN) + 1e-5f);
    }
    __syncthreads();
    if (t < HIDN)
        g_hact[b * HIDN + t] =
            fmaxf((shid[t] - sstat[0]) * sstat[1] * ln_g[t] + ln_b[t], 0.f);
}

__global__ void __launch_bounds__(256) k_head2(
    const float* __restrict__ fh_w, const float* __restrict__ fh_b)
{
    __shared__ float sH[BSZ * 17];
    int t = threadIdx.x;
    for (int i = t; i < BSZ * HIDN; i += 256)
        sH[(i >> 4) * 17 + (i & 15)] = g_hact[i];
    __syncthreads();
    int b = t & 31;
    int grp = blockIdx.x * 8 + (t >> 5);
    float h[HIDN];
#pragma unroll
    for (int i = 0; i < HIDN; ++i) h[i] = sH[b * 17 + i];

    const float4* wp = (const float4*)(fh_w + (size_t)grp * KSZ * HIDN);
    float lg[KSZ]; float mx = -1e30f;
#pragma unroll
    for (int k = 0; k < KSZ; ++k) {
        float4 w0 = wp[k * 4 + 0], w1 = wp[k * 4 + 1], w2 = wp[k * 4 + 2], w3 = wp[k * 4 + 3];
        float a = fh_b[grp * KSZ + k];
        a += h[0]*w0.x + h[1]*w0.y + h[2]*w0.z + h[3]*w0.w;
        a += h[4]*w1.x + h[5]*w1.y + h[6]*w1.z + h[7]*w1.w;
        a += h[8]*w2.x + h[9]*w2.y + h[10]*w2.z + h[11]*w2.w;
        a += h[12]*w3.x + h[13]*w3.y + h[14]*w3.z + h[15]*w3.w;
        lg[k] = a; mx = fmaxf(mx, a);
    }
    float sum = 0.f;
#pragma unroll
    for (int k = 0; k < KSZ; ++k) { lg[k] = expf(lg[k] - mx); sum += lg[k]; }
    float inv = 1.0f / sum;
    float* out = g_coeffs + (size_t)b * (CSZ * MSZ * KSZ) + grp * KSZ;
    ((float4*)out)[0] = make_float4(lg[0]*inv, lg[1]*inv, lg[2]*inv, lg[3]*inv);
    ((float4*)out)[1] = make_float4(lg[4]*inv, lg[5]*inv, lg[6]*inv, lg[7]*inv);
}

// per-plane fused resize/DFT/mask/iDFT/resize, conjugate-symmetric S3/S4
__global__ void __launch_bounds__(256) k_spec(
    const float* __restrict__ x,
    const float* __restrict__ br, const float* __restrict__ bi)
{
    __shared__ __align__(16) float sm[10544];
    float2* B1 = (float2*)sm;                  // 1792 f2
    float2* B2 = (float2*)(sm + 3584);         // 1792 f2
    float*  BX = sm + 7168;                    // 3248 floats (x plane / CS table)
    float2* CS = (float2*)(sm + 7168);
    float*  sCo = sm + 10416;                  // 128

    int plane = blockIdx.x;
    int t = threadIdx.x, warp = t >> 5, lane = t & 31;
    const float* xp = x + (size_t)plane * NPIX;

    for (int i = t; i < NPIX; i += 256) BX[i] = xp[i];
    if (t < 128) sCo[t] = g_coeffs[(size_t)plane * 128 + t];
    for (int i = t; i < 1792; i += 256) B1[i] = g_FwRT[i];
    __syncthreads();

    // ---- S2: T1[h][v] = sum_w x[h][w] * FwRT[w][v] -> B2 ----
    {
        float2 acc[7];
#pragma unroll
        for (int r = 0; r < 7; ++r) acc[r] = make_float2(0.f, 0.f);
        int h0 = warp * 7;
        for (int w = 0; w < HH; w += 2) {
            float2 f0 = B1[w * WFQ + lane];
            float2 f1 = B1[(w + 1) * WFQ + lane];
#pragma unroll
            for (int r = 0; r < 7; ++r) {
                float2 a = *(const float2*)&BX[(h0 + r) * HH + w];
                acc[r].x += a.x * f0.x + a.y * f1.x;
                acc[r].y += a.x * f0.y + a.y * f1.y;
            }
        }
#pragma unroll
        for (int r = 0; r < 7; ++r) B2[(h0 + r) * WFQ + lane] = acc[r];
    }
    __syncthreads();

    // load CS table (overwrites x-plane region)
    for (int i = t; i < 29 * HH; i += 256) CS[i] = g_CS[i];
    __syncthreads();

    int pg[4] = {warp, warp + 8, warp + 16, warp + 24};

    // ---- S3: X = Fh*T1 (conjugate-symmetric), mask -> Y in B1 ----
    {
        ull PQr[4] = {0, 0, 0, 0}, PQi[4] = {0, 0, 0, 0};
#pragma unroll 2
        for (int h = 0; h < HH; ++h) {
            float2 tt = B2[h * WFQ + lane];
            ull ttr = d_dup(tt.x), tti = d_dup(tt.y);
#pragma unroll
            for (int g = 0; g < 4; ++g) {
                if (pg[g] < 29) {
                    ull cs = *(ull*)&CS[pg[g] * HH + h];
                    PQr[g] = d_fma2(cs, ttr, PQr[g]);
                    PQi[g] = d_fma2(cs, tti, PQi[g]);
                }
            }
        }
#pragma unroll
        for (int g = 0; g < 4; ++g) {
            int p = pg[g];
            if (p < 29) {
                float2 pr = d_unpack(PQr[g]), pi = d_unpack(PQi[g]);
                // X[p] = (Pr+Qi, Pi-Qr)
                {
                    int u = p;
                    float xr = pr.x + pi.y, xi = pi.x - pr.y;
                    const float* co = sCo + ((u / 14) * 4 + (lane >> 3)) * KSZ;
                    float mr = 0.f, mi = 0.f;
#pragma unroll
                    for (int k = 0; k < KSZ; ++k) {
                        int bidx = k * (HH * WFQ) + u * WFQ + lane;
                        mr += co[k] * br[bidx];
                        mi += co[k] * bi[bidx];
                    }
                    B1[u * WFQ + lane] = make_float2(xr * mr - xi * mi, xr * mi + xi * mr);
                }
                if (p >= 1 && p <= 27) {
                    int u = HH - p;
                    float xr = pr.x - pi.y, xi = pi.x + pr.y;
                    const float* co = sCo + ((u / 14) * 4 + (lane >> 3)) * KSZ;
                    float mr = 0.f, mi = 0.f;
#pragma unroll
                    for (int k = 0; k < KSZ; ++k) {
                        int bidx = k * (HH * WFQ) + u * WFQ + lane;
                        mr += co[k] * br[bidx];
                        mi += co[k] * bi[bidx];
                    }
                    B1[u * WFQ + lane] = make_float2(xr * mr - xi * mi, xr * mi + xi * mr);
                }
            }
        }
    }
    __syncthreads();

    // ---- S4: T2 = Gh*Y (conjugate-symmetric) -> B2 ----
    {
        ull PQr[4] = {0, 0, 0, 0}, PQi[4] = {0, 0, 0, 0};
#pragma unroll 2
        for (int u = 0; u < HH; ++u) {
            float2 yy = B1[u * WFQ + lane];
            ull yr = d_dup(yy.x), yi = d_dup(yy.y);
#pragma unroll
            for (int g = 0; g < 4; ++g) {
                if (pg[g] < 29) {
                    ull cs = *(ull*)&CS[pg[g] * HH + u];
                    PQr[g] = d_fma2(cs, yr, PQr[g]);
                    PQi[g] = d_fma2(cs, yi, PQi[g]);
                }
            }
        }
#pragma unroll
        for (int g = 0; g < 4; ++g) {
            int p = pg[g];
            if (p < 29) {
                float2 pr = d_unpack(PQr[g]), pi = d_unpack(PQi[g]);
                // T2[p] = (SumCYr - SumSYi, SumCYi + SumSYr)
                B2[p * WFQ + lane] = make_float2(pr.x - pi.y, pi.x + pr.y);
                if (p >= 1 && p <= 27)
                    B2[(HH - p) * WFQ + lane] = make_float2(pr.x + pi.y, pi.x - pr.y);
            }
        }
    }
    __syncthreads();

    // ---- S5: y[h][w0] = Re( T2[h][:] . GwT[:][w0] ) ----
    for (int i = t; i < 1792; i += 256) B1[i] = g_GwT[i];
    __syncthreads();
    float* outp = g_yspec + (size_t)plane * NPIX;
    for (int grp = 0; grp < 2; ++grp) {
        int nr = grp ? 3 : 4;
        float a1[4] = {0.f, 0.f, 0.f, 0.f};
        float a2[4] = {0.f, 0.f, 0.f, 0.f};
        for (int v = 0; v < WFQ; ++v) {
            float2 g1 = B1[v * HH + lane];
            float2 g2 = (lane < 24) ? B1[v * HH + 32 + lane] : make_float2(0.f, 0.f);
#pragma unroll
            for (int r = 0; r < 4; ++r) {
                if (r < nr) {
                    float2 tt = B2[(warp + 8 * (grp * 4 + r)) * WFQ + v];
                    a1[r] += tt.x * g1.x - tt.y * g1.y;
                    a2[r] += tt.x * g2.x - tt.y * g2.y;
                }
            }
        }
#pragma unroll
        for (int r = 0; r < 4; ++r) {
            if (r < nr) {
                int h = warp + 8 * (grp * 4 + r);
                outp[h * HH + lane] = a1[r];
                if (lane < 24) outp[h * HH + 32 + lane] = a2[r];
            }
        }
    }
}

// W -> bf16 hi/lo split
__global__ void k_wsplit(const float* __restrict__ W) {
    int i = blockIdx.x * blockDim.x + threadIdx.x;
    float v = W[i];
    __nv_bfloat16 hi = __float2bfloat16(v);
    __nv_bfloat16 lo = __float2bfloat16(v - __bfloat162float(hi));
    g_whl[0][i] = hi;
    g_whl[1][i] = lo;
}

// ---------------- 1x1 conv via mma.sync bf16 split precision (R7) -----------
#define KC 32
#define ASTR 40
__global__ void __launch_bounds__(256) k_conv_mma() {
    __shared__ __nv_bfloat16 cAh[128 * ASTR];
    __shared__ __nv_bfloat16 cAl[128 * ASTR];
    __shared__ __nv_bfloat16 cBh[128 * ASTR];
    __shared__ __nv_bfloat16 cBl[128 * ASTR];

    int t = threadIdx.x, wid = t >> 5, lane = t & 31;
    int p0 = blockIdx.x * 128;
    int mo = blockIdx.y * 128;
    int b  = blockIdx.z;
    const float* Y = g_yspec + (size_t)b * CSZ * NPIX;
    float* Out = g_yconv + (size_t)b * CSZ * NPIX;

    int wm = (wid & 1) * 64;
    int wn = (wid >> 1) * 32;
    int qr = lane >> 2, qc = lane & 3;

    float acc[16][4];
#pragma unroll
    for (int i = 0; i < 16; ++i)
#pragma unroll
        for (int j = 0; j < 4; ++j) acc[i][j] = 0.f;

    for (int kk = 0; kk < CSZ; kk += KC) {
        {
            int r = t >> 1, cg = (t & 1) * 16;
            const __nv_bfloat16* w0 = &g_whl[0][(size_t)(mo + r) * CSZ + kk + cg];
            const __nv_bfloat16* w1 = &g_whl[1][(size_t)(mo + r) * CSZ + kk + cg];
            *(uint4*)&cAh[r * ASTR + cg]     = *(const uint4*)w0;
            *(uint4*)&cAh[r * ASTR + cg + 8] = *(const uint4*)(w0 + 8);
            *(uint4*)&cAl[r * ASTR + cg]     = *(const uint4*)w1;
            *(uint4*)&cAl[r * ASTR + cg + 8] = *(const uint4*)(w1 + 8);
        }
        {
            int c = t >> 3, pg2 = (t & 7) * 16;
#pragma unroll
            for (int j = 0; j < 16; j += 4) {
                float4 v = make_float4(0.f, 0.f, 0.f, 0.f);
                if (p0 + pg2 + j < NPIX)
                    v = *(const float4*)&Y[(size_t)(kk + c) * NPIX + p0 + pg2 + j];
                float vv[4] = {v.x, v.y, v.z, v.w};
#pragma unroll
                for (int e = 0; e < 4; ++e) {
                    __nv_bfloat16 hi, lo; bsplit(vv[e], hi, lo);
                    cBh[(pg2 + j + e) * ASTR + c] = hi;
                    cBl[(pg2 + j + e) * ASTR + c] = lo;
                }
            }
        }
        __syncthreads();

#pragma unroll
        for (int ks = 0; ks < 2; ++ks) {
            int cb = ks * 16 + qc * 2;
            uint32_t afh[4][4], afl[4][4];
#pragma unroll
            for (int mf = 0; mf < 4; ++mf) {
                lda_frags(cAh, ASTR, wm + mf * 16 + qr, cb, afh[mf]);
                lda_frags(cAl, ASTR, wm + mf * 16 + qr, cb, afl[mf]);
            }
            uint32_t bf[4][2];
#pragma unroll
            for (int nf = 0; nf < 4; ++nf)
                ldb_frag(cBh, ASTR, wn + nf * 8 + qr, cb, bf[nf]);
#pragma unroll
            for (int mf = 0; mf < 4; ++mf)
#pragma unroll
                for (int nf = 0; nf < 4; ++nf) {
                    mma_bf16(acc[mf * 4 + nf], afh[mf], bf[nf]);
                    mma_bf16(acc[mf * 4 + nf], afl[mf], bf[nf]);
                }
#pragma unroll
            for (int nf = 0; nf < 4; ++nf)
                ldb_frag(cBl, ASTR, wn + nf * 8 + qr, cb, bf[nf]);
#pragma unroll
            for (int mf = 0; mf < 4; ++mf)
#pragma unroll
                for (int nf = 0; nf < 4; ++nf)
                    mma_bf16(acc[mf * 4 + nf], afh[mf], bf[nf]);
        }
        __syncthreads();
    }

#pragma unroll
    for (int mf = 0; mf < 4; ++mf)
#pragma unroll
        for (int nf = 0; nf < 4; ++nf) {
            float* a = acc[mf * 4 + nf];
            int r = mo + wm + mf * 16 + qr;
            int cl = p0 + wn + nf * 8 + qc * 2;
            if (cl < NPIX) {
                *(float2*)&Out[(size_t)r * NPIX + cl] = make_float2(a[0], a[1]);
                *(float2*)&Out[(size_t)(r + 8) * NPIX + cl] = make_float2(a[2], a[3]);
            }
        }
}

__global__ void k_bnstat(const float* __restrict__ bn_g, const float* __restrict__ bn_b) {
    int o = blockIdx.x, t = threadIdx.x;
    float s1 = 0.f, s2 = 0.f;
    for (int b = 0; b < BSZ; ++b) {
        const float* p = g_yconv + (size_t)b * CSZ * NPIX + (size_t)o * NPIX;
        for (int i = t; i < NPIX; i += 256) { float v = p[i]; s1 += v; s2 += v * v; }
    }
    __shared__ double r1[256], r2[256];
    r1[t] = s1; r2[t] = s2; __syncthreads();
    for (int st = 128; st > 0; st >>= 1) {
        if (t < st) { r1[t] += r1[t + st]; r2[t] += r2[t + st]; }
        __syncthreads();
    }
    if (t == 0) {
        double N = (double)BSZ * NPIX;
        double mean = r1[0] / N, var = r2[0] / N - (r1[0] / N) * (r1[0] / N);
        float inv = (float)(1.0 / sqrt(var + 1e-5));
        float A = bn_g[o] * inv;
        g_bnA[o] = A;
        g_bnB[o] = bn_b[o] - (float)mean * A;
    }
}

__global__ void k_bnapply(float* __restrict__ out) {
    int i4 = blockIdx.x * blockDim.x + threadIdx.x;
    int c = (i4 / (NPIX / 4)) % CSZ;
    float A = g_bnA[c], Bv = g_bnB[c];
    float4 v = ((const float4*)g_yconv)[i4];
    v.x = v.x * A + Bv; v.y = v.y * A + Bv; v.z = v.z * A + Bv; v.w = v.w * A + Bv;
    ((float4*)out)[i4] = v;
}

extern "C" void kernel_launch(void* const* d_in, const int* in_sizes, int n_in,
                              void* d_out, int out_size) {
    const float* x      = (const float*)d_in[0];
    const float* fc1_w  = (const float*)d_in[1];
    const float* fc1_b  = (const float*)d_in[2];
    const float* ln_g   = (const float*)d_in[3];
    const float* ln_b   = (const float*)d_in[4];
    const float* fh_w   = (const float*)d_in[5];
    const float* fh_b   = (const float*)d_in[6];
    const float* br     = (const float*)d_in[7];
    const float* bi     = (const float*)d_in[8];
    const float* conv_w = (const float*)d_in[9];
    const float* bn_g   = (const float*)d_in[10];
    const float* bn_b   = (const float*)d_in[11];
    (void)in_sizes; (void)n_in; (void)out_size;

    k_init0<<<1, 256>>>();
    k_init1<<<45, 256>>>();
    k_ctx<<<BSZ * CSZ, 128>>>(x);
    k_head1<<<BSZ, 256>>>(fc1_w, fc1_b, ln_g, ln_b);
    k_head2<<<512, 256>>>(fh_w, fh_b);
    k_wsplit<<<256, 256>>>(conv_w);
    k_spec<<<BSZ * CSZ, 256>>>(x, br, bi);
    dim3 gc(25, 2, BSZ);
    k_conv_mma<<<gc, 256>>>();
    k_bnstat<<<CSZ, 256>>>(bn_g, bn_b);
    k_bnapply<<<(BSZ * CSZ * NPIX) / 1024, 256>>>((float*)d_out);
}

// round 11
// speedup vs baseline: 1.4094x; 1.4094x over previous
#include <cuda_runtime.h>
#include <cuda_bf16.h>
#include <stdint.h>
#include <math.h>

#define BSZ 32
#define CSZ 256
#define HH  56
#define WFQ 32
#define WWK 62
#define NPIX 3136
#define MSZ 16
#define KSZ 8
#define HIDN 16
#define PI_D 3.141592653589793238462643383279502884

typedef unsigned long long ull;

__device__ __forceinline__ ull d_fma2(ull a, ull b, ull c) {
    ull d;
    asm("fma.rn.f32x2 %0, %1, %2, %3;" : "=l"(d) : "l"(a), "l"(b), "l"(c));
    return d;
}
__device__ __forceinline__ ull d_dup(float x) {
    ull r;
    asm("mov.b64 %0, {%1, %1};" : "=l"(r) : "f"(x));
    return r;
}
__device__ __forceinline__ float2 d_unpack(ull v) {
    float2 r;
    asm("mov.b64 {%0, %1}, %2;" : "=f"(r.x), "=f"(r.y) : "l"(v));
    return r;
}
__device__ __forceinline__ void mma_bf16(float* d, const uint32_t* a, const uint32_t* b) {
    asm("mma.sync.aligned.m16n8k16.row.col.f32.bf16.bf16.f32 "
        "{%0,%1,%2,%3}, {%4,%5,%6,%7}, {%8,%9}, {%0,%1,%2,%3};"
        : "+f"(d[0]), "+f"(d[1]), "+f"(d[2]), "+f"(d[3])
        : "r"(a[0]), "r"(a[1]), "r"(a[2]), "r"(a[3]), "r"(b[0]), "r"(b[1]));
}
__device__ __forceinline__ void bsplit(float v, __nv_bfloat16& hi, __nv_bfloat16& lo) {
    hi = __float2bfloat16(v);
    lo = __float2bfloat16(v - __bfloat162float(hi));
}
__device__ __forceinline__ void lda_frags(const __nv_bfloat16* P, int stride, int r0, int cb, uint32_t* f) {
    f[0] = *(const uint32_t*)&P[r0 * stride + cb];
    f[1] = *(const uint32_t*)&P[(r0 + 8) * stride + cb];
    f[2] = *(const uint32_t*)&P[r0 * stride + cb + 8];
    f[3] = *(const uint32_t*)&P[(r0 + 8) * stride + cb + 8];
}
__device__ __forceinline__ void ldb_frag(const __nv_bfloat16* P, int stride, int n0, int cb, uint32_t* f) {
    f[0] = *(const uint32_t*)&P[n0 * stride + cb];
    f[1] = *(const uint32_t*)&P[n0 * stride + cb + 8];
}

// ----------------------------- device scratch -------------------------------
__device__ float  g_ctx[BSZ * CSZ];
__device__ float  g_hact[BSZ * HIDN];
__device__ float  g_coeffs[BSZ * CSZ * MSZ * KSZ];
__device__ float  g_yspec[(size_t)BSZ * CSZ * NPIX];
__device__ float  g_yconv[(size_t)BSZ * CSZ * NPIX];
__device__ float  g_bnA[CSZ], g_bnB[CSZ];
__device__ float  g_s1[CSZ], g_s2[CSZ];
__device__ __nv_bfloat16 g_whl[2][CSZ * CSZ];

__device__ float2 g_FwRT[HH * WFQ];
__device__ float2 g_Fh[HH * HH];
__device__ float2 g_Gh[HH * HH];
__device__ float2 g_GwT[WFQ * HH];

__device__ double g_Rf[WWK * HH];
__device__ double g_Rb[HH * WWK];
__device__ double g_tw62r[WWK], g_tw62i[WWK];

__device__ double rz_fwd(int j, int i) {
    double s = (j + 0.5) * (56.0 / 62.0) - 0.5;
    double w = fmax(0.0, 1.0 - fabs(s - (double)i));
    double denom = 0.0;
    int i0 = (int)floor(s);
    for (int q = i0; q <= i0 + 1; ++q)
        if (q >= 0 && q < 56) denom += fmax(0.0, 1.0 - fabs(s - (double)q));
    return w / denom;
}
__device__ double rz_bwd(int j, int i) {
    double ks = 62.0 / 56.0;
    double s = (j + 0.5) * ks - 0.5;
    double w = fmax(0.0, 1.0 - fabs(s - (double)i) / ks);
    double denom = 0.0;
    int lo = (int)ceil(s - ks), hi = (int)floor(s + ks);
    if (lo < 0) lo = 0;
    if (hi > 61) hi = 61;
    for (int q = lo; q <= hi; ++q)
        denom += fmax(0.0, 1.0 - fabs(s - (double)q) / ks);
    return w / denom;
}

__global__ void k_init0() {
    int t = threadIdx.x;
    if (t < WWK) { double a = -2.0 * PI_D * t / 62.0; g_tw62r[t] = cos(a); g_tw62i[t] = sin(a); }
    for (int i = t; i < WWK * HH; i += blockDim.x) g_Rf[i] = rz_fwd(i / HH, i % HH);
    for (int i = t; i < HH * WWK; i += blockDim.x) g_Rb[i] = rz_bwd(i / WWK, i % WWK);
}

__global__ void k_init1() {
    const double SC = 1.0 / sqrt(56.0 * 62.0);
    int total = 1792 + 1792 + 3136 + 3136;
    for (int idx = blockIdx.x * blockDim.x + threadIdx.x; idx < total; idx += gridDim.x * blockDim.x) {
        if (idx < 1792) {
            int w0 = idx / WFQ, v = idx % WFQ;
            double ar = 0, ai = 0;
            for (int w = 0; w < WWK; ++w) {
                double r = g_Rf[w * HH + w0]; int m = (v * w) % WWK;
                ar += g_tw62r[m] * r; ai += g_tw62i[m] * r;
            }
            g_FwRT[w0 * WFQ + v] = make_float2((float)(ar * SC), (float)(ai * SC));
        } else if (idx < 3584) {
            int j = idx - 1792; int v = j / HH, w0 = j % HH;
            double cv = (v == 0 || v == 31) ? 1.0 : 2.0;
            double ar = 0, ai = 0;
            for (int w = 0; w < WWK; ++w) {
                double r = g_Rb[w0 * WWK + w]; int m = (v * w) % WWK;
                ar += g_tw62r[m] * r; ai -= g_tw62i[m] * r;
            }
            g_GwT[v * HH + w0] = make_float2((float)(ar * cv * SC), (float)(ai * cv * SC));
        } else if (idx < 6720) {
            int j = idx - 3584; int u = j / HH, h = j % HH;
            double a = -2.0 * PI_D * ((u * h) % HH) / 56.0;
            g_Fh[u * HH + h] = make_float2((float)cos(a), (float)sin(a));
        } else {
            int j = idx - 6720; int h = j / HH, u = j % HH;
            double a = 2.0 * PI_D * ((u * h) % HH) / 56.0;
            g_Gh[h * HH + u] = make_float2((float)cos(a), (float)(sin(a)));
        }
    }
}

__global__ void k_ctx(const float* __restrict__ x) {
    int plane = blockIdx.x;
    const float4* p = (const float4*)(x + (size_t)plane * NPIX);
    float s = 0.f;
    for (int i = threadIdx.x; i < NPIX / 4; i += blockDim.x) {
        float4 v = p[i]; s += v.x + v.y + v.z + v.w;
    }
    for (int o = 16; o > 0; o >>= 1) s += __shfl_xor_sync(0xffffffffu, s, o);
    __shared__ float red[4];
    int warp = threadIdx.x >> 5, lane = threadIdx.x & 31;
    if (lane == 0) red[warp] = s;
    __syncthreads();
    if (threadIdx.x == 0)
        g_ctx[plane] = (red[0] + red[1] + red[2] + red[3]) * (1.0f / NPIX);
}

__global__ void __launch_bounds__(256) k_head1(
    const float* __restrict__ fc1_w, const float* __restrict__ fc1_b,
    const float* __restrict__ ln_g,  const float* __restrict__ ln_b)
{
    int b = blockIdx.x, t = threadIdx.x;
    int warp = t >> 5, lane = t & 31;
    __shared__ float sctx[CSZ];
    __shared__ float shid[HIDN];
    __shared__ float sstat[2];
    sctx[t] = g_ctx[b * CSZ + t];
    __syncthreads();
    for (int rep = 0; rep < 2; ++rep) {
        int hidx = warp * 2 + rep;
        float acc = 0.f;
        for (int c = lane; c < CSZ; c += 32) acc += sctx[c] * fc1_w[hidx * CSZ + c];
        for (int o = 16; o > 0; o >>= 1) acc += __shfl_xor_sync(0xffffffffu, acc, o);
        if (lane == 0) shid[hidx] = acc + fc1_b[hidx];
    }
    __syncthreads();
    if (t == 0) {
        float mu = 0.f;
        for (int i = 0; i < HIDN; ++i) mu += shid[i];
        mu *= (1.0f / HIDN);
        float var = 0.f;
        for (int i = 0; i < HIDN; ++i) { float d = shid[i] - mu; var += d * d; }
        sstat[0] = mu; sstat[1] = rsqrtf(var * (1.0f / HIDN) + 1e-5f);
    }
    __syncthreads();
    if (t < HIDN)
        g_hact[b * HIDN + t] =
            fmaxf((shid[t] - sstat[0]) * sstat[1] * ln_g[t] + ln_b[t], 0.f);
}

__global__ void __launch_bounds__(256) k_head2(
    const float* __restrict__ fh_w, const float* __restrict__ fh_b)
{
    __shared__ float sH[BSZ * 17];
    int t = threadIdx.x;
    for (int i = t; i < BSZ * HIDN; i += 256)
        sH[(i >> 4) * 17 + (i & 15)] = g_hact[i];
    __syncthreads();
    int b = t & 31;
    int grp = blockIdx.x * 8 + (t >> 5);
    float h[HIDN];
#pragma unroll
    for (int i = 0; i < HIDN; ++i) h[i] = sH[b * 17 + i];

    const float4* wp = (const float4*)(fh_w + (size_t)grp * KSZ * HIDN);
    float lg[KSZ]; float mx = -1e30f;
#pragma unroll
    for (int k = 0; k < KSZ; ++k) {
        float4 w0 = wp[k * 4 + 0], w1 = wp[k * 4 + 1], w2 = wp[k * 4 + 2], w3 = wp[k * 4 + 3];
        float a = fh_b[grp * KSZ + k];
        a += h[0]*w0.x + h[1]*w0.y + h[2]*w0.z + h[3]*w0.w;
        a += h[4]*w1.x + h[5]*w1.y + h[6]*w1.z + h[7]*w1.w;
        a += h[8]*w2.x + h[9]*w2.y + h[10]*w2.z + h[11]*w2.w;
        a += h[12]*w3.x + h[13]*w3.y + h[14]*w3.z + h[15]*w3.w;
        lg[k] = a; mx = fmaxf(mx, a);
    }
    float sum = 0.f;
#pragma unroll
    for (int k = 0; k < KSZ; ++k) { lg[k] = expf(lg[k] - mx); sum += lg[k]; }
    float inv = 1.0f / sum;
    float* out = g_coeffs + (size_t)b * (CSZ * MSZ * KSZ) + grp * KSZ;
    ((float4*)out)[0] = make_float4(lg[0]*inv, lg[1]*inv, lg[2]*inv, lg[3]*inv);
    ((float4*)out)[1] = make_float4(lg[4]*inv, lg[5]*inv, lg[6]*inv, lg[7]*inv);
}

// per-plane fused resize/DFT/mask/iDFT/resize (R4/R7 scalar f32x2, inline mask)
__global__ void __launch_bounds__(256) k_spec(
    const float* __restrict__ x,
    const float* __restrict__ br, const float* __restrict__ bi)
{
    __shared__ __align__(16) float sm[10432];
    float2* B1 = (float2*)sm;
    float2* B2 = (float2*)(sm + 3584);
    float*  BX = sm + 7168;
    float4* Bq = (float4*)(sm + 7168);
    float*  sCo = sm + 10304;

    int plane = blockIdx.x;
    int t = threadIdx.x, warp = t >> 5, lane = t & 31;
    const float* xp = x + (size_t)plane * NPIX;

    for (int i = t; i < NPIX; i += 256) BX[i] = xp[i];
    if (t < 128) sCo[t] = g_coeffs[(size_t)plane * 128 + t];
    for (int i = t; i < 1792; i += 256) B1[i] = g_FwRT[i];
    __syncthreads();

    {
        float2 acc[7];
#pragma unroll
        for (int r = 0; r < 7; ++r) acc[r] = make_float2(0.f, 0.f);
        int h0 = warp * 7;
        for (int w = 0; w < HH; w += 2) {
            float2 f0 = B1[w * WFQ + lane];
            float2 f1 = B1[(w + 1) * WFQ + lane];
#pragma unroll
            for (int r = 0; r < 7; ++r) {
                float2 a = *(const float2*)&BX[(h0 + r) * HH + w];
                acc[r].x += a.x * f0.x + a.y * f1.x;
                acc[r].y += a.x * f0.y + a.y * f1.y;
            }
        }
#pragma unroll
        for (int r = 0; r < 7; ++r) B2[(h0 + r) * WFQ + lane] = acc[r];
    }
    __syncthreads();

    for (int half = 0; half < 2; ++half) {
        int ub = half * 28;
        for (int i = t; i < 14 * HH; i += 256) {
            int p = i / HH, h = i % HH;
            float2 f0 = g_Fh[(ub + 2 * p) * HH + h];
            float2 f1 = g_Fh[(ub + 2 * p + 1) * HH + h];
            Bq[i] = make_float4(f0.x, f1.x, f0.y, f1.y);
        }
        __syncthreads();
        ull ar[2] = {0, 0}, ai[2] = {0, 0};
        int p1ok = (warp + 8) < 14;
        for (int h = 0; h < HH; ++h) {
            float2 tt = B2[h * WFQ + lane];
            ull ttx = d_dup(tt.x), tty = d_dup(tt.y), ttyn = d_dup(-tt.y);
            float4 q0 = Bq[warp * HH + h];
            ull fx0 = *(ull*)&q0.x, fy0 = *(ull*)&q0.z;
            ar[0] = d_fma2(fx0, ttx, ar[0]); ar[0] = d_fma2(fy0, ttyn, ar[0]);
            ai[0] = d_fma2(fy0, ttx, ai[0]); ai[0] = d_fma2(fx0, tty, ai[0]);
            if (p1ok) {
                float4 q1 = Bq[(warp + 8) * HH + h];
                ull fx1 = *(ull*)&q1.x, fy1 = *(ull*)&q1.z;
                ar[1] = d_fma2(fx1, ttx, ar[1]); ar[1] = d_fma2(fy1, ttyn, ar[1]);
                ai[1] = d_fma2(fy1, ttx, ai[1]); ai[1] = d_fma2(fx1, tty, ai[1]);
            }
        }
#pragma unroll
        for (int pp = 0; pp < 2; ++pp) {
            int p = warp + 8 * pp;
            if (p < 14) {
                float2 re = d_unpack(ar[pp]), im = d_unpack(ai[pp]);
#pragma unroll
                for (int j = 0; j < 2; ++j) {
                    int u = ub + 2 * p + j;
                    const float* co = sCo + ((u / 14) * 4 + (lane >> 3)) * KSZ;
                    float mr = 0.f, mi = 0.f;
#pragma unroll
                    for (int k = 0; k < KSZ; ++k) {
                        int bidx = k * (HH * WFQ) + u * WFQ + lane;
                        mr += co[k] * br[bidx];
                        mi += co[k] * bi[bidx];
                    }
                    float xr = j ? re.y : re.x, xi = j ? im.y : im.x;
                    B1[u * WFQ + lane] = make_float2(xr * mr - xi * mi, xr * mi + xi * mr);
                }
            }
        }
        __syncthreads();
    }

    for (int half = 0; half < 2; ++half) {
        int hb = half * 28;
        for (int i = t; i < 14 * HH; i += 256) {
            int p = i / HH, u = i % HH;
            float2 f0 = g_Gh[(hb + 2 * p) * HH + u];
            float2 f1 = g_Gh[(hb + 2 * p + 1) * HH + u];
            Bq[i] = make_float4(f0.x, f1.x, f0.y, f1.y);
        }
        __syncthreads();
        ull ar[2] = {0, 0}, ai[2] = {0, 0};
        int p1ok = (warp + 8) < 14;
        for (int u = 0; u < HH; ++u) {
            float2 yy = B1[u * WFQ + lane];
            ull yx = d_dup(yy.x), yyp = d_dup(yy.y), yyn = d_dup(-yy.y);
            float4 q0 = Bq[warp * HH + u];
            ull fx0 = *(ull*)&q0.x, fy0 = *(ull*)&q0.z;
            ar[0] = d_fma2(fx0, yx, ar[0]); ar[0] = d_fma2(fy0, yyn, ar[0]);
            ai[0] = d_fma2(fy0, yx, ai[0]); ai[0] = d_fma2(fx0, yyp, ai[0]);
            if (p1ok) {
                float4 q1 = Bq[(warp + 8) * HH + u];
                ull fx1 = *(ull*)&q1.x, fy1 = *(ull*)&q1.z;
                ar[1] = d_fma2(fx1, yx, ar[1]); ar[1] = d_fma2(fy1, yyn, ar[1]);
                ai[1] = d_fma2(fy1, yx, ai[1]); ai[1] = d_fma2(fx1, yyp, ai[1]);
            }
        }
#pragma unroll
        for (int pp = 0; pp < 2; ++pp) {
            int p = warp + 8 * pp;
            if (p < 14) {
                float2 re = d_unpack(ar[pp]), im = d_unpack(ai[pp]);
                B2[(hb + 2 * p + 0) * WFQ + lane] = make_float2(re.x, im.x);
                B2[(hb + 2 * p + 1) * WFQ + lane] = make_float2(re.y, im.y);
            }
        }
        __syncthreads();
    }

    for (int i = t; i < 1792; i += 256) B1[i] = g_GwT[i];
    __syncthreads();
    float* outp = g_yspec + (size_t)plane * NPIX;
    for (int grp = 0; grp < 2; ++grp) {
        int nr = grp ? 3 : 4;
        float a1[4] = {0.f, 0.f, 0.f, 0.f};
        float a2[4] = {0.f, 0.f, 0.f, 0.f};
        for (int v = 0; v < WFQ; ++v) {
            float2 g1 = B1[v * HH + lane];
            float2 g2 = (lane < 24) ? B1[v * HH + 32 + lane] : make_float2(0.f, 0.f);
#pragma unroll
            for (int r = 0; r < 4; ++r) {
                if (r < nr) {
                    float2 tt = B2[(warp + 8 * (grp * 4 + r)) * WFQ + v];
                    a1[r] += tt.x * g1.x - tt.y * g1.y;
                    a2[r] += tt.x * g2.x - tt.y * g2.y;
                }
            }
        }
#pragma unroll
        for (int r = 0; r < 4; ++r) {
            if (r < nr) {
                int h = warp + 8 * (grp * 4 + r);
                outp[h * HH + lane] = a1[r];
                if (lane < 24) outp[h * HH + 32 + lane] = a2[r];
            }
        }
    }
}

// W -> bf16 hi/lo split; block 0 also zeroes BN accumulators
__global__ void k_wsplit(const float* __restrict__ W) {
    int i = blockIdx.x * blockDim.x + threadIdx.x;
    float v = W[i];
    __nv_bfloat16 hi = __float2bfloat16(v);
    __nv_bfloat16 lo = __float2bfloat16(v - __bfloat162float(hi));
    g_whl[0][i] = hi;
    g_whl[1][i] = lo;
    if (blockIdx.x == 0) { g_s1[threadIdx.x] = 0.f; g_s2[threadIdx.x] = 0.f; }
}

// ---------------- 1x1 conv via mma.sync bf16 split precision + BN sums ------
#define KC 32
#define ASTR 40
__global__ void __launch_bounds__(256) k_conv_mma() {
    __shared__ __nv_bfloat16 cAh[128 * ASTR];
    __shared__ __nv_bfloat16 cAl[128 * ASTR];
    __shared__ __nv_bfloat16 cBh[128 * ASTR];
    __shared__ __nv_bfloat16 cBl[128 * ASTR];
    __shared__ float sS1[128], sS2[128];

    int t = threadIdx.x, wid = t >> 5, lane = t & 31;
    int p0 = blockIdx.x * 128;
    int mo = blockIdx.y * 128;
    int b  = blockIdx.z;
    const float* Y = g_yspec + (size_t)b * CSZ * NPIX;
    float* Out = g_yconv + (size_t)b * CSZ * NPIX;

    int wm = (wid & 1) * 64;
    int wn = (wid >> 1) * 32;
    int qr = lane >> 2, qc = lane & 3;

    if (t < 128) { sS1[t] = 0.f; sS2[t] = 0.f; }

    float acc[16][4];
#pragma unroll
    for (int i = 0; i < 16; ++i)
#pragma unroll
        for (int j = 0; j < 4; ++j) acc[i][j] = 0.f;

    for (int kk = 0; kk < CSZ; kk += KC) {
        {
            int r = t >> 1, cg = (t & 1) * 16;
            const __nv_bfloat16* w0 = &g_whl[0][(size_t)(mo + r) * CSZ + kk + cg];
            const __nv_bfloat16* w1 = &g_whl[1][(size_t)(mo + r) * CSZ + kk + cg];
            *(uint4*)&cAh[r * ASTR + cg]     = *(const uint4*)w0;
            *(uint4*)&cAh[r * ASTR + cg + 8] = *(const uint4*)(w0 + 8);
            *(uint4*)&cAl[r * ASTR + cg]     = *(const uint4*)w1;
            *(uint4*)&cAl[r * ASTR + cg + 8] = *(const uint4*)(w1 + 8);
        }
        {
            int c = t >> 3, pg2 = (t & 7) * 16;
#pragma unroll
            for (int j = 0; j < 16; j += 4) {
                float4 v = make_float4(0.f, 0.f, 0.f, 0.f);
                if (p0 + pg2 + j < NPIX)
                    v = *(const float4*)&Y[(size_t)(kk + c) * NPIX + p0 + pg2 + j];
                float vv[4] = {v.x, v.y, v.z, v.w};
#pragma unroll
                for (int e = 0; e < 4; ++e) {
                    __nv_bfloat16 hi, lo; bsplit(vv[e], hi, lo);
                    cBh[(pg2 + j + e) * ASTR + c] = hi;
                    cBl[(pg2 + j + e) * ASTR + c] = lo;
                }
            }
        }
        __syncthreads();

#pragma unroll
        for (int ks = 0; ks < 2; ++ks) {
            int cb = ks * 16 + qc * 2;
            uint32_t afh[4][4], afl[4][4];
#pragma unroll
            for (int mf = 0; mf < 4; ++mf) {
                lda_frags(cAh, ASTR, wm + mf * 16 + qr, cb, afh[mf]);
                lda_frags(cAl, ASTR, wm + mf * 16 + qr, cb, afl[mf]);
            }
            uint32_t bf[4][2];
#pragma unroll
            for (int nf = 0; nf < 4; ++nf)
                ldb_frag(cBh, ASTR, wn + nf * 8 + qr, cb, bf[nf]);
#pragma unroll
            for (int mf = 0; mf < 4; ++mf)
#pragma unroll
                for (int nf = 0; nf < 4; ++nf) {
                    mma_bf16(acc[mf * 4 + nf], afh[mf], bf[nf]);
                    mma_bf16(acc[mf * 4 + nf], afl[mf], bf[nf]);
                }
#pragma unroll
            for (int nf = 0; nf < 4; ++nf)
                ldb_frag(cBl, ASTR, wn + nf * 8 + qr, cb, bf[nf]);
#pragma unroll
            for (int mf = 0; mf < 4; ++mf)
#pragma unroll
                for (int nf = 0; nf < 4; ++nf)
                    mma_bf16(acc[mf * 4 + nf], afh[mf], bf[nf]);
        }
        __syncthreads();
    }

    // store outputs + per-channel BN partial sums
#pragma unroll
    for (int mf = 0; mf < 4; ++mf) {
        float s1a = 0.f, s2a = 0.f, s1b = 0.f, s2b = 0.f;
#pragma unroll
        for (int nf = 0; nf < 4; ++nf) {
            float* a = acc[mf * 4 + nf];
            int r = mo + wm + mf * 16 + qr;
            int cl = p0 + wn + nf * 8 + qc * 2;
            if (cl < NPIX) {
                *(float2*)&Out[(size_t)r * NPIX + cl] = make_float2(a[0], a[1]);
                *(float2*)&Out[(size_t)(r + 8) * NPIX + cl] = make_float2(a[2], a[3]);
            }
            s1a += a[0] + a[1]; s2a += a[0]*a[0] + a[1]*a[1];
            s1b += a[2] + a[3]; s2b += a[2]*a[2] + a[3]*a[3];
        }
#pragma unroll
        for (int o = 1; o <= 2; o <<= 1) {
            s1a += __shfl_xor_sync(0xffffffffu, s1a, o);
            s2a += __shfl_xor_sync(0xffffffffu, s2a, o);
            s1b += __shfl_xor_sync(0xffffffffu, s1b, o);
            s2b += __shfl_xor_sync(0xffffffffu, s2b, o);
        }
        if (qc == 0) {
            int lr = wm + mf * 16 + qr;
            atomicAdd(&sS1[lr], s1a); atomicAdd(&sS2[lr], s2a);
            atomicAdd(&sS1[lr + 8], s1b); atomicAdd(&sS2[lr + 8], s2b);
        }
    }
    __syncthreads();
    if (t < 128) {
        atomicAdd(&g_s1[mo + t], sS1[t]);
        atomicAdd(&g_s2[mo + t], sS2[t]);
    }
}

__global__ void k_bnfin(const float* __restrict__ bn_g, const float* __restrict__ bn_b) {
    int o = threadIdx.x;
    double N = (double)BSZ * NPIX;
    double mean = (double)g_s1[o] / N;
    double var = (double)g_s2[o] / N - mean * mean;
    float A = bn_g[o] * (float)(1.0 / sqrt(var + 1e-5));
    g_bnA[o] = A;
    g_bnB[o] = bn_b[o] - (float)mean * A;
}

__global__ void k_bnapply(float* __restrict__ out) {
    int i4 = blockIdx.x * blockDim.x + threadIdx.x;
    int c = (i4 / (NPIX / 4)) % CSZ;
    float A = g_bnA[c], Bv = g_bnB[c];
    float4 v = ((const float4*)g_yconv)[i4];
    v.x = v.x * A + Bv; v.y = v.y * A + Bv; v.z = v.z * A + Bv; v.w = v.w * A + Bv;
    ((float4*)out)[i4] = v;
}

extern "C" void kernel_launch(void* const* d_in, const int* in_sizes, int n_in,
                              void* d_out, int out_size) {
    const float* x      = (const float*)d_in[0];
    const float* fc1_w  = (const float*)d_in[1];
    const float* fc1_b  = (const float*)d_in[2];
    const float* ln_g   = (const float*)d_in[3];
    const float* ln_b   = (const float*)d_in[4];
    const float* fh_w   = (const float*)d_in[5];
    const float* fh_b   = (const float*)d_in[6];
    const float* br     = (const float*)d_in[7];
    const float* bi     = (const float*)d_in[8];
    const float* conv_w = (const float*)d_in[9];
    const float* bn_g   = (const float*)d_in[10];
    const float* bn_b   = (const float*)d_in[11];
    (void)in_sizes; (void)n_in; (void)out_size;

    k_init0<<<1, 256>>>();
    k_init1<<<40, 256>>>();
    k_ctx<<<BSZ * CSZ, 128>>>(x);
    k_head1<<<BSZ, 256>>>(fc1_w, fc1_b, ln_g, ln_b);
    k_head2<<<512, 256>>>(fh_w, fh_b);
    k_wsplit<<<256, 256>>>(conv_w);
    k_spec<<<BSZ * CSZ, 256>>>(x, br, bi);
    dim3 gc(25, 2, BSZ);
    k_conv_mma<<<gc, 256>>>();
    k_bnfin<<<1, 256>>>(bn_g, bn_b);
    k_bnapply<<<(BSZ * CSZ * NPIX) / 1024, 256>>>((float*)d_out);
}